// round 6
// baseline (speedup 1.0000x reference)
#include <cuda_runtime.h>
#include <cuda_bf16.h>
#include <cstdint>

// GCN sparse aggregation: out[r,:] += vals[e] * embeds[cols[e],:]
// N=100000 nodes, E=1600000 edges, D=64, fp32.
//
// Round 5: 2-launch pipeline with fixed-capacity per-node edge buckets.
//   1) place: each thread handles 4 edges (vectorized loads, 4 independent
//      atomicAdd allocations -> MLP=4), stores packed {col,val} into
//      bucket[r*CAP + pos]. No histogram, no scan.
//   2) aggregate: one warp per node, lanes own a float2 of the D=64 row,
//      walk the node's contiguous bucket, accumulate in regs, coalesced
//      float2 store. Resets cnt[node]=0 to restore the invariant for the
//      next (identical) execution. Output fully overwritten -> no zero pass.
//
// Degree ~ Poisson(16); P(deg >= 64) < 1e-17 per node -> CAP=64 is safe for
// this fixed dataset.

#define D_FEAT 64
#define NV 100000
#define NE 1600000
#define CAP 64

__device__ int  g_cnt[NV];                     // zero-init; aggregate restores 0
__device__ int2 g_bucket[(size_t)NV * CAP];    // {col, val_bits} per slot

__global__ void __launch_bounds__(256) place_kernel(
    const int4*   __restrict__ rows4,
    const int4*   __restrict__ cols4,
    const float4* __restrict__ vals4,
    int n_quads)
{
    int t = blockIdx.x * blockDim.x + threadIdx.x;
    if (t >= n_quads) return;

    int4   r = __ldg(&rows4[t]);
    int4   c = __ldg(&cols4[t]);
    float4 v = __ldg(&vals4[t]);

    // 4 independent atomic allocations in flight (hide ATOMG ~318 cyc).
    int p0 = atomicAdd(&g_cnt[r.x], 1);
    int p1 = atomicAdd(&g_cnt[r.y], 1);
    int p2 = atomicAdd(&g_cnt[r.z], 1);
    int p3 = atomicAdd(&g_cnt[r.w], 1);

    g_bucket[(size_t)r.x * CAP + p0] = make_int2(c.x, __float_as_int(v.x));
    g_bucket[(size_t)r.y * CAP + p1] = make_int2(c.y, __float_as_int(v.y));
    g_bucket[(size_t)r.z * CAP + p2] = make_int2(c.z, __float_as_int(v.z));
    g_bucket[(size_t)r.w * CAP + p3] = make_int2(c.w, __float_as_int(v.w));
}

__global__ void __launch_bounds__(256) place_tail_kernel(
    const int*   __restrict__ rows,
    const int*   __restrict__ cols,
    const float* __restrict__ vals,
    int start, int n_edges)
{
    int e = start + blockIdx.x * blockDim.x + threadIdx.x;
    if (e >= n_edges) return;
    int r = rows[e];
    int pos = atomicAdd(&g_cnt[r], 1);
    g_bucket[(size_t)r * CAP + pos] = make_int2(cols[e], __float_as_int(vals[e]));
}

__global__ void __launch_bounds__(256) aggregate_kernel(
    const float2* __restrict__ embeds2,   // [NV, 32] float2
    float2*       __restrict__ out2,      // [NV, 32] float2
    int n_nodes)
{
    int w    = (blockIdx.x * blockDim.x + threadIdx.x) >> 5;  // node = warp
    int lane = threadIdx.x & 31;
    if (w >= n_nodes) return;

    int cnt = g_cnt[w];                    // broadcast load
    __syncwarp();
    if (lane == 0) g_cnt[w] = 0;           // restore invariant for next run

    const int2* __restrict__ bucket = g_bucket + (size_t)w * CAP;

    float ax = 0.f, ay = 0.f;
    int j = 0;
    for (; j + 3 < cnt; j += 4) {
        int2 p0 = __ldg(&bucket[j]);
        int2 p1 = __ldg(&bucket[j + 1]);
        int2 p2 = __ldg(&bucket[j + 2]);
        int2 p3 = __ldg(&bucket[j + 3]);
        float2 x0 = __ldg(&embeds2[(size_t)p0.x * 32 + lane]);
        float2 x1 = __ldg(&embeds2[(size_t)p1.x * 32 + lane]);
        float2 x2 = __ldg(&embeds2[(size_t)p2.x * 32 + lane]);
        float2 x3 = __ldg(&embeds2[(size_t)p3.x * 32 + lane]);
        float v0 = __int_as_float(p0.y);
        float v1 = __int_as_float(p1.y);
        float v2 = __int_as_float(p2.y);
        float v3 = __int_as_float(p3.y);
        ax += v0 * x0.x; ay += v0 * x0.y;
        ax += v1 * x1.x; ay += v1 * x1.y;
        ax += v2 * x2.x; ay += v2 * x2.y;
        ax += v3 * x3.x; ay += v3 * x3.y;
    }
    for (; j < cnt; ++j) {
        int2 p = __ldg(&bucket[j]);
        float v = __int_as_float(p.y);
        float2 x = __ldg(&embeds2[(size_t)p.x * 32 + lane]);
        ax += v * x.x; ay += v * x.y;
    }
    out2[(size_t)w * 32 + lane] = make_float2(ax, ay);
}

extern "C" void kernel_launch(void* const* d_in, const int* in_sizes, int n_in,
                              void* d_out, int out_size)
{
    const int*   rows   = (const int*)d_in[0];
    const int*   cols   = (const int*)d_in[1];
    const float* vals   = (const float*)d_in[2];
    const float* embeds = (const float*)d_in[3];
    int n_edges = in_sizes[0];
    if (n_edges > NE) n_edges = NE;
    int n_nodes = out_size / D_FEAT;
    if (n_nodes > NV) n_nodes = NV;

    float* out = (float*)d_out;

    // 1) place edges into per-node buckets (4 edges per thread)
    int n_quads = n_edges >> 2;
    if (n_quads > 0) {
        int threads = 256;
        int blocks = (n_quads + threads - 1) / threads;
        place_kernel<<<blocks, threads>>>(
            (const int4*)rows, (const int4*)cols, (const float4*)vals, n_quads);
    }
    int tail_start = n_quads << 2;
    if (tail_start < n_edges) {
        int tail = n_edges - tail_start;
        place_tail_kernel<<<(tail + 255) / 256, 256>>>(
            rows, cols, vals, tail_start, n_edges);
    }

    // 2) aggregate: warp per node, resets g_cnt for next run
    {
        long long total = (long long)n_nodes * 32;
        int threads = 256;
        int blocks = (int)((total + threads - 1) / threads);
        aggregate_kernel<<<blocks, threads>>>(
            (const float2*)embeds, (float2*)out, n_nodes);
    }
}

// round 7
// speedup vs baseline: 2.5169x; 2.5169x over previous
#include <cuda_runtime.h>
#include <cuda_bf16.h>
#include <cstdint>

// GCN sparse aggregation: out[r,:] += vals[e] * embeds[cols[e],:]
// N=100000 nodes, E=1600000 edges, D=64, fp32.
//
// Round 6: CSR counting-sort (L2-safe 84MB footprint — round 5 showed the
// fat-bucket layout blows the 126MB L2 and goes DRAM-latency-bound) with
// MLP-optimized preprocessing: hist and place each handle 4 edges/thread via
// vectorized loads so 4 atomics are in flight per thread (ATOMG ~318cyc / 4).
//   1) hist  : count[rows[e]]++                 (x4 vectorized)
//   2) scan1 : block-exclusive prefix, resets count for next run
//   3) scan3 : fused block-offset scan + finalize rowstart/cursor
//   4) place : slot = cursor[r]++; edge[slot] = {col,val}   (x4 vectorized)
//   5) aggregate: warp per node, lane owns float2 of D=64 row, unroll-4
//      independent loads, reg accumulation, coalesced store (overwrites out,
//      so no zero pass).

#define D_FEAT 64
#define NV 100000
#define NE 1600000
#define SCAN_BS 512
#define NB ((NV + SCAN_BS - 1) / SCAN_BS)   // 196

__device__ int  g_count[NV];        // zero at load; scan1 restores 0 each run
__device__ int  g_cursor[NV];
__device__ int  g_rowstart[NV + 1];
__device__ int  g_blocksum[NB];
__device__ int2 g_edge[NE];         // {col, val_bits}, grouped by row

// ---- 1) histogram: 4 edges per thread, 4 independent REDs ----
__global__ void __launch_bounds__(256) hist_kernel(
    const int4* __restrict__ rows4, int n_quads)
{
    int t = blockIdx.x * blockDim.x + threadIdx.x;
    if (t >= n_quads) return;
    int4 r = __ldg(&rows4[t]);
    atomicAdd(&g_count[r.x], 1);
    atomicAdd(&g_count[r.y], 1);
    atomicAdd(&g_count[r.z], 1);
    atomicAdd(&g_count[r.w], 1);
}

__global__ void __launch_bounds__(256) hist_tail_kernel(
    const int* __restrict__ rows, int start, int n_edges)
{
    int e = start + blockIdx.x * blockDim.x + threadIdx.x;
    if (e < n_edges) atomicAdd(&g_count[rows[e]], 1);
}

// ---- 2) block-exclusive scan; resets g_count ----
__global__ void __launch_bounds__(SCAN_BS) scan1_kernel(int n_nodes) {
    __shared__ int sm[SCAN_BS];
    int g = blockIdx.x * SCAN_BS + threadIdx.x;
    int v = 0;
    if (g < n_nodes) {
        v = g_count[g];
        g_count[g] = 0;                 // invariant for next execution
    }
    sm[threadIdx.x] = v;
    __syncthreads();
    for (int off = 1; off < SCAN_BS; off <<= 1) {
        int t = (threadIdx.x >= off) ? sm[threadIdx.x - off] : 0;
        __syncthreads();
        sm[threadIdx.x] += t;
        __syncthreads();
    }
    if (g < n_nodes) g_cursor[g] = sm[threadIdx.x] - v;
    if (threadIdx.x == SCAN_BS - 1) g_blocksum[blockIdx.x] = sm[SCAN_BS - 1];
}

// ---- 3) fused block-offset scan + finalize ----
__global__ void __launch_bounds__(SCAN_BS) scan3_kernel(int n_nodes, int n_edges) {
    __shared__ int bs[256];
    int tid = threadIdx.x;
    if (tid < 256) bs[tid] = (tid < NB) ? g_blocksum[tid] : 0;
    __syncthreads();
    for (int off = 1; off < 256; off <<= 1) {
        int t = (tid >= off && tid < 256) ? bs[tid - off] : 0;
        __syncthreads();
        if (tid < 256) bs[tid] += t;
        __syncthreads();
    }
    int blockoff = (blockIdx.x == 0) ? 0 : bs[blockIdx.x - 1];
    int g = blockIdx.x * SCAN_BS + tid;
    if (g < n_nodes) {
        int rs = g_cursor[g] + blockoff;
        g_rowstart[g] = rs;
        g_cursor[g]   = rs;
    }
    if (g == 0) g_rowstart[n_nodes] = n_edges;
}

// ---- 4) place: 4 edges per thread, 4 independent ATOMGs ----
__global__ void __launch_bounds__(256) place_kernel(
    const int4*   __restrict__ rows4,
    const int4*   __restrict__ cols4,
    const float4* __restrict__ vals4,
    int n_quads)
{
    int t = blockIdx.x * blockDim.x + threadIdx.x;
    if (t >= n_quads) return;

    int4   r = __ldg(&rows4[t]);
    int4   c = __ldg(&cols4[t]);
    float4 v = __ldg(&vals4[t]);

    int p0 = atomicAdd(&g_cursor[r.x], 1);
    int p1 = atomicAdd(&g_cursor[r.y], 1);
    int p2 = atomicAdd(&g_cursor[r.z], 1);
    int p3 = atomicAdd(&g_cursor[r.w], 1);

    g_edge[p0] = make_int2(c.x, __float_as_int(v.x));
    g_edge[p1] = make_int2(c.y, __float_as_int(v.y));
    g_edge[p2] = make_int2(c.z, __float_as_int(v.z));
    g_edge[p3] = make_int2(c.w, __float_as_int(v.w));
}

__global__ void __launch_bounds__(256) place_tail_kernel(
    const int*   __restrict__ rows,
    const int*   __restrict__ cols,
    const float* __restrict__ vals,
    int start, int n_edges)
{
    int e = start + blockIdx.x * blockDim.x + threadIdx.x;
    if (e >= n_edges) return;
    int r = rows[e];
    int pos = atomicAdd(&g_cursor[r], 1);
    g_edge[pos] = make_int2(cols[e], __float_as_int(vals[e]));
}

// ---- 5) aggregate: warp per node ----
__global__ void __launch_bounds__(256) aggregate_kernel(
    const float2* __restrict__ embeds2,   // [NV, 32] float2
    float2*       __restrict__ out2,      // [NV, 32] float2
    int n_nodes)
{
    int w    = (blockIdx.x * blockDim.x + threadIdx.x) >> 5;
    int lane = threadIdx.x & 31;
    if (w >= n_nodes) return;

    int i   = g_rowstart[w];
    int end = g_rowstart[w + 1];

    float ax = 0.f, ay = 0.f;

    for (; i + 3 < end; i += 4) {
        int2 p0 = __ldg(&g_edge[i]);
        int2 p1 = __ldg(&g_edge[i + 1]);
        int2 p2 = __ldg(&g_edge[i + 2]);
        int2 p3 = __ldg(&g_edge[i + 3]);
        float2 x0 = __ldg(&embeds2[(size_t)p0.x * 32 + lane]);
        float2 x1 = __ldg(&embeds2[(size_t)p1.x * 32 + lane]);
        float2 x2 = __ldg(&embeds2[(size_t)p2.x * 32 + lane]);
        float2 x3 = __ldg(&embeds2[(size_t)p3.x * 32 + lane]);
        float v0 = __int_as_float(p0.y);
        float v1 = __int_as_float(p1.y);
        float v2 = __int_as_float(p2.y);
        float v3 = __int_as_float(p3.y);
        ax += v0 * x0.x; ay += v0 * x0.y;
        ax += v1 * x1.x; ay += v1 * x1.y;
        ax += v2 * x2.x; ay += v2 * x2.y;
        ax += v3 * x3.x; ay += v3 * x3.y;
    }
    for (; i < end; ++i) {
        int2 p = __ldg(&g_edge[i]);
        float v = __int_as_float(p.y);
        float2 x = __ldg(&embeds2[(size_t)p.x * 32 + lane]);
        ax += v * x.x; ay += v * x.y;
    }
    out2[(size_t)w * 32 + lane] = make_float2(ax, ay);
}

extern "C" void kernel_launch(void* const* d_in, const int* in_sizes, int n_in,
                              void* d_out, int out_size)
{
    const int*   rows   = (const int*)d_in[0];
    const int*   cols   = (const int*)d_in[1];
    const float* vals   = (const float*)d_in[2];
    const float* embeds = (const float*)d_in[3];
    int n_edges = in_sizes[0];
    if (n_edges > NE) n_edges = NE;
    int n_nodes = out_size / D_FEAT;
    if (n_nodes > NV) n_nodes = NV;

    float* out = (float*)d_out;

    int n_quads    = n_edges >> 2;
    int tail_start = n_quads << 2;

    {   // 1) histogram (x4)
        if (n_quads > 0) {
            int blocks = (n_quads + 255) / 256;
            hist_kernel<<<blocks, 256>>>((const int4*)rows, n_quads);
        }
        if (tail_start < n_edges) {
            int tail = n_edges - tail_start;
            hist_tail_kernel<<<(tail + 255) / 256, 256>>>(rows, tail_start, n_edges);
        }
    }
    {   // 2-3) scan
        scan1_kernel<<<NB, SCAN_BS>>>(n_nodes);
        scan3_kernel<<<NB, SCAN_BS>>>(n_nodes, n_edges);
    }
    {   // 4) place (x4)
        if (n_quads > 0) {
            int blocks = (n_quads + 255) / 256;
            place_kernel<<<blocks, 256>>>(
                (const int4*)rows, (const int4*)cols, (const float4*)vals, n_quads);
        }
        if (tail_start < n_edges) {
            int tail = n_edges - tail_start;
            place_tail_kernel<<<(tail + 255) / 256, 256>>>(
                rows, cols, vals, tail_start, n_edges);
        }
    }
    {   // 5) aggregate
        long long total = (long long)n_nodes * 32;
        int blocks = (int)((total + 255) / 256);
        aggregate_kernel<<<blocks, 256>>>(
            (const float2*)embeds, (float2*)out, n_nodes);
    }
}